// round 1
// baseline (speedup 1.0000x reference)
#include <cuda_runtime.h>

// Problem constants
#define NHEADS 16
#define DHEAD  64
#define NTILE  64     // number of q/kv tiles per head
#define TILE   128    // tokens per tile
#define SEQ    8192
#define HID    1024

// Scratch: tiled Q/K/V/O, layout [NH][NTILE][TILE][D]
__device__ float g_q[NHEADS * NTILE * TILE * DHEAD];
__device__ float g_k[NHEADS * NTILE * TILE * DHEAD];
__device__ float g_v[NHEADS * NTILE * TILE * DHEAD];
__device__ float g_o[NHEADS * NTILE * TILE * DHEAD];

// seq index s -> (tile n, within-tile p)
// s = t*1024 + h*32 + w ; t=ntt*2+tt, h=nth*8+th, w=ntw*8+tw
// n = (ntt*4+nth)*4+ntw ; p = (tt*8+th)*8+tw
__device__ __forceinline__ void seq_to_tile(int s, int& n, int& p) {
    int t = s >> 10;
    int h = (s >> 5) & 31;
    int w = s & 31;
    n = (((t >> 1) * 4 + (h >> 3)) * 4 + (w >> 3));
    p = (((t & 1) * 8 + (h & 7)) * 8 + (w & 7));
}

// ---------------------------------------------------------------------------
// QKV projection GEMM: C[s, head*64+d] = X[s,:] @ W[:, head*64+d]
// written directly into tiled layout. 64x64 block, 256 threads, 4x4/thread.
// grid: (HID/64, SEQ/64, 3)   z selects (Wq->g_q, Wk->g_k, Wv->g_v)
// ---------------------------------------------------------------------------
__global__ __launch_bounds__(256) void qkv_gemm(
    const float* __restrict__ X,
    const float* __restrict__ Wq,
    const float* __restrict__ Wk,
    const float* __restrict__ Wv)
{
    const float* W = (blockIdx.z == 0) ? Wq : (blockIdx.z == 1) ? Wk : Wv;
    float* Out = (blockIdx.z == 0) ? g_q : (blockIdx.z == 1) ? g_k : g_v;

    const int m0 = blockIdx.y * 64;
    const int n0 = blockIdx.x * 64;      // one head per n-block (64 == DHEAD)
    const int head = n0 >> 6;

    __shared__ float As[16][65];   // [k][m], padded
    __shared__ float Bs[16][64];   // [k][n]

    const int tid = threadIdx.x;
    const int tx = tid & 15;
    const int ty = tid >> 4;

    float c[4][4] = {};

    for (int kk = 0; kk < HID; kk += 16) {
        #pragma unroll
        for (int l = 0; l < 4; l++) {
            int e = tid + l * 256;
            int m = e >> 4, k = e & 15;
            As[k][m] = X[(m0 + m) * HID + kk + k];
        }
        #pragma unroll
        for (int l = 0; l < 4; l++) {
            int e = tid + l * 256;
            int k = e >> 6, nn = e & 63;
            Bs[k][nn] = W[(kk + k) * HID + n0 + nn];
        }
        __syncthreads();
        #pragma unroll
        for (int k = 0; k < 16; k++) {
            float a[4];
            #pragma unroll
            for (int i = 0; i < 4; i++) a[i] = As[k][ty * 4 + i];
            float4 b = *(const float4*)&Bs[k][tx * 4];
            #pragma unroll
            for (int i = 0; i < 4; i++) {
                c[i][0] += a[i] * b.x;
                c[i][1] += a[i] * b.y;
                c[i][2] += a[i] * b.z;
                c[i][3] += a[i] * b.w;
            }
        }
        __syncthreads();
    }

    #pragma unroll
    for (int i = 0; i < 4; i++) {
        int srow = m0 + ty * 4 + i;
        int n, p;
        seq_to_tile(srow, n, p);
        float4 v = make_float4(c[i][0], c[i][1], c[i][2], c[i][3]);
        *(float4*)&Out[((head * NTILE + n) * TILE + p) * DHEAD + tx * 4] = v;
    }
}

// ---------------------------------------------------------------------------
// Sliding-tile attention. grid = NHEADS*NTILE blocks, 128 threads
// (one query row per thread). K/V streamed in 64-key chunks through smem.
// Online softmax with lazy rescale.
// ---------------------------------------------------------------------------
__global__ __launch_bounds__(128) void attn_kernel()
{
    const int bid = blockIdx.x;
    const int head = bid >> 6;
    const int n = bid & 63;
    const int tid = threadIdx.x;

    __shared__ float4 Ks[64 * 16];   // [key][d4]
    __shared__ float4 Vs[64 * 16];

    const float4* qp = (const float4*)&g_q[((head * NTILE + n) * TILE + tid) * DHEAD];
    float4 q[16];
    #pragma unroll
    for (int i = 0; i < 16; i++) q[i] = qp[i];

    float4 o[16];
    #pragma unroll
    for (int i = 0; i < 16; i++) o[i] = make_float4(0.f, 0.f, 0.f, 0.f);

    float m = -1e30f, l = 0.f;

    // kv window (verified against reference _dim_window):
    // t-dim (nt=4, w=3): center = clip(ntt,1,2), kv_t = center-1+{0,1,2}
    // h/w-dim (nt=4, w=2): center = clip(nt,1,3), kv = center-1+{0,1}
    const int ntt = n >> 4, nth = (n >> 2) & 3, ntw = n & 3;
    const int ct = min(max(ntt, 1), 2);
    const int ch = min(max(nth, 1), 3);
    const int cw = min(max(ntw, 1), 3);

    for (int kk = 0; kk < 12; kk++) {
        const int it = kk >> 2, ih = (kk >> 1) & 1, iw = kk & 1;
        const int kvn = ((ct - 1 + it) * 4 + (ch - 1 + ih)) * 4 + (cw - 1 + iw);
        const float4* kbase = (const float4*)&g_k[((head * NTILE + kvn) * TILE) * DHEAD];
        const float4* vbase = (const float4*)&g_v[((head * NTILE + kvn) * TILE) * DHEAD];

        for (int cchunk = 0; cchunk < 2; cchunk++) {
            __syncthreads();
            #pragma unroll
            for (int r = 0; r < 8; r++) {
                int e = tid + r * 128;          // 1024 float4 = 64 keys x 16
                Ks[e] = kbase[cchunk * 1024 + e];
                Vs[e] = vbase[cchunk * 1024 + e];
            }
            __syncthreads();

            for (int j = 0; j < 64; j++) {
                float s = 0.f;
                #pragma unroll
                for (int d = 0; d < 16; d++) {
                    float4 kv = Ks[j * 16 + d];
                    s += q[d].x * kv.x + q[d].y * kv.y + q[d].z * kv.z + q[d].w * kv.w;
                }
                s *= 0.125f;   // 1/sqrt(64)
                if (s > m) {
                    float corr = __expf(m - s);
                    l *= corr;
                    #pragma unroll
                    for (int d = 0; d < 16; d++) {
                        o[d].x *= corr; o[d].y *= corr; o[d].z *= corr; o[d].w *= corr;
                    }
                    m = s;
                }
                float p = __expf(s - m);
                l += p;
                #pragma unroll
                for (int d = 0; d < 16; d++) {
                    float4 vv = Vs[j * 16 + d];
                    o[d].x += p * vv.x; o[d].y += p * vv.y;
                    o[d].z += p * vv.z; o[d].w += p * vv.w;
                }
            }
        }
    }

    const float inv = 1.f / l;
    float4* op = (float4*)&g_o[((head * NTILE + n) * TILE + tid) * DHEAD];
    #pragma unroll
    for (int i = 0; i < 16; i++) {
        o[i].x *= inv; o[i].y *= inv; o[i].z *= inv; o[i].w *= inv;
        op[i] = o[i];
    }
}

// ---------------------------------------------------------------------------
// Output projection: out[s, :] = O_seq[s, :] @ Wo, where
// O_seq[s, head*64+d] = g_o[head][n(s)][p(s)][d]  (the _from_tiles inverse)
// ---------------------------------------------------------------------------
__global__ __launch_bounds__(256) void oproj_gemm(
    const float* __restrict__ Wo, float* __restrict__ out)
{
    const int m0 = blockIdx.y * 64;
    const int n0 = blockIdx.x * 64;

    __shared__ float As[16][65];
    __shared__ float Bs[16][64];

    const int tid = threadIdx.x;
    const int tx = tid & 15;
    const int ty = tid >> 4;

    float c[4][4] = {};

    for (int kk = 0; kk < HID; kk += 16) {
        #pragma unroll
        for (int l = 0; l < 4; l++) {
            int e = tid + l * 256;
            int m = e >> 4, k = e & 15;
            int srow = m0 + m;
            int n, p;
            seq_to_tile(srow, n, p);
            int kcol = kk + k;
            As[k][m] = g_o[(((kcol >> 6) * NTILE + n) * TILE + p) * DHEAD + (kcol & 63)];
        }
        #pragma unroll
        for (int l = 0; l < 4; l++) {
            int e = tid + l * 256;
            int k = e >> 6, nn = e & 63;
            Bs[k][nn] = Wo[(kk + k) * HID + n0 + nn];
        }
        __syncthreads();
        #pragma unroll
        for (int k = 0; k < 16; k++) {
            float a[4];
            #pragma unroll
            for (int i = 0; i < 4; i++) a[i] = As[k][ty * 4 + i];
            float4 b = *(const float4*)&Bs[k][tx * 4];
            #pragma unroll
            for (int i = 0; i < 4; i++) {
                c[i][0] += a[i] * b.x;
                c[i][1] += a[i] * b.y;
                c[i][2] += a[i] * b.z;
                c[i][3] += a[i] * b.w;
            }
        }
        __syncthreads();
    }

    #pragma unroll
    for (int i = 0; i < 4; i++) {
        int srow = m0 + ty * 4 + i;
        float4 v = make_float4(c[i][0], c[i][1], c[i][2], c[i][3]);
        *(float4*)&out[srow * HID + n0 + tx * 4] = v;
    }
}

extern "C" void kernel_launch(void* const* d_in, const int* in_sizes, int n_in,
                              void* d_out, int out_size)
{
    const float* X  = (const float*)d_in[0];
    const float* Wq = (const float*)d_in[1];
    const float* Wk = (const float*)d_in[2];
    const float* Wv = (const float*)d_in[3];
    const float* Wo = (const float*)d_in[4];
    float* out = (float*)d_out;

    dim3 gqkv(HID / 64, SEQ / 64, 3);
    qkv_gemm<<<gqkv, 256>>>(X, Wq, Wk, Wv);

    attn_kernel<<<NHEADS * NTILE, 128>>>();

    dim3 gop(HID / 64, SEQ / 64, 1);
    oproj_gemm<<<gop, 256>>>(Wo, out);
}